// round 1
// baseline (speedup 1.0000x reference)
#include <cuda_runtime.h>
#include <cstddef>

// Problem constants (fixed by setup_inputs)
#define RB   12      // regions
#define LB   32      // latent
#define MB   16      // message dim
#define HHB  32      // GRU hidden
#define HFB  64      // flow hidden
#define EB   132     // edges = R*(R-1)
#define BTOT 64      // batch
#define NGROUP 12    // batch groups -> 144 blocks
#define NBLOCKS (NGROUP*RB)
#define NTHREADS 192 // 6 warps (max batches per group)
#define MAXWB 6

__device__ unsigned g_bar[NGROUP];

struct SmemLayout {
    // weights (transposed for lane-contiguous inner loops)
    float mwT[11*528];    // [slot][k*16+m], per-edge stride padded to 528 (bank-split halves)
    float awT[11*512];    // [slot][m*32+l]
    float mb [11*16];
    float gswT[32*32];    // [i*32+o]
    float gcwT[32*32];
    float gsb[32];
    float lwT[64*64];     // [i*64+o]
    float lb[64];
    float owT[64*32];     // [oh*32+l]
    float ob[32];
    float wihT[32*96];    // [i*96+j]
    float whhT[32*96];
    float bih[96];
    float bhh[96];
    int   elist[11];
    int   slist[11];
    // per-batch activations
    float zs  [MAXWB][RB][LB];
    float incS[MAXWB][LB];
    float hg  [MAXWB][HHB];
    float hbuf[MAXWB][HFB];
    float meanS[MAXWB][2][MB];
};

__device__ __forceinline__ float fsig(float x) { return 1.0f / (1.0f + __expf(-x)); }

__global__ void nv_init_kernel() {
    if (threadIdx.x < NGROUP) g_bar[threadIdx.x] = 0u;
}

__global__ void __launch_bounds__(NTHREADS, 1) nv_main_kernel(
    const float* __restrict__ z0,  const float* __restrict__ h0,
    const float* __restrict__ mean_w, const float* __restrict__ mean_b,
    const float* __restrict__ add_w,
    const float* __restrict__ gsw, const float* __restrict__ gsb_g,
    const float* __restrict__ gcw,
    const float* __restrict__ lw,  const float* __restrict__ lb_g,
    const float* __restrict__ ow,  const float* __restrict__ ob_g,
    const float* __restrict__ wih, const float* __restrict__ whh,
    const float* __restrict__ bih_g, const float* __restrict__ bhh_g,
    const int* __restrict__ src_idx, const int* __restrict__ tgt_idx,
    int T,
    float* __restrict__ zt, float* __restrict__ hf, float* __restrict__ ms)
{
    extern __shared__ char smraw[];
    SmemLayout& sm = *reinterpret_cast<SmemLayout*>(smraw);
    const int tid = threadIdx.x;
    const int g = blockIdx.x / RB;
    const int r = blockIdx.x % RB;

    const int nb = (g < 4) ? 6 : 5;                 // batches in this group
    const int b0 = g * 5 + (g < 4 ? g : 4);         // first batch index

    // ---- build incoming-edge list for region r ----
    for (int e = tid; e < EB; e += NTHREADS) {
        if (tgt_idx[e] == r) {
            int s = src_idx[e];
            int slot = (s < r) ? s : s - 1;
            sm.elist[slot] = e;
            sm.slist[slot] = s;
        }
    }
    __syncthreads();

    // ---- cache weights to smem (transposed) ----
    for (int idx = tid; idx < 11*MB*LB; idx += NTHREADS) {
        int slot = idx / (MB*LB); int rem = idx % (MB*LB);
        int m = rem / LB, k = rem % LB;
        int e = sm.elist[slot];
        sm.mwT[slot*528 + k*16 + m] = mean_w[((size_t)e*MB + m)*LB + k];
    }
    for (int idx = tid; idx < 11*LB*MB; idx += NTHREADS) {
        int slot = idx / (LB*MB); int rem = idx % (LB*MB);
        int l = rem / MB, m = rem % MB;
        int e = sm.elist[slot];
        sm.awT[slot*512 + m*32 + l] = add_w[((size_t)e*LB + l)*MB + m];
    }
    for (int idx = tid; idx < 11*MB; idx += NTHREADS) {
        int slot = idx / MB, m = idx % MB;
        sm.mb[idx] = mean_b[sm.elist[slot]*MB + m];
    }
    for (int idx = tid; idx < LB*LB; idx += NTHREADS) {
        int o = idx / LB, i = idx % LB;
        sm.gswT[i*32 + o] = gsw[((size_t)r*LB + o)*LB + i];
        sm.gcwT[i*32 + o] = gcw[((size_t)r*LB + o)*LB + i];
    }
    if (tid < LB) sm.gsb[tid] = gsb_g[r*LB + tid];
    for (int idx = tid; idx < HFB*2*LB; idx += NTHREADS) {
        int o = idx / (2*LB), i = idx % (2*LB);
        sm.lwT[i*64 + o] = lw[((size_t)r*HFB + o)*(2*LB) + i];
    }
    if (tid < HFB) sm.lb[tid] = lb_g[r*HFB + tid];
    for (int idx = tid; idx < LB*HFB; idx += NTHREADS) {
        int l = idx / HFB, o = idx % HFB;
        sm.owT[o*32 + l] = ow[((size_t)r*LB + l)*HFB + o];
    }
    if (tid < LB) sm.ob[tid] = ob_g[r*LB + tid];
    for (int idx = tid; idx < 3*HHB*LB; idx += NTHREADS) {
        int j = idx / LB, i = idx % LB;
        sm.wihT[i*96 + j] = wih[((size_t)r*3*HHB + j)*LB + i];
        sm.whhT[i*96 + j] = whh[((size_t)r*3*HHB + j)*HHB + i];
    }
    if (tid < 96) { sm.bih[tid] = bih_g[r*96 + tid]; sm.bhh[tid] = bhh_g[r*96 + tid]; }

    // ---- init per-batch state ----
    const int wb   = tid >> 5;
    const int lane = tid & 31;
    if (wb < nb) {
        int b = b0 + wb;
        #pragma unroll
        for (int rr = 0; rr < RB; rr++)
            sm.zs[wb][rr][lane] = z0[((size_t)b*RB + rr)*LB + lane];
        sm.hg[wb][lane] = h0[((size_t)b*RB + r)*HHB + lane];
    }
    __syncthreads();

    float hnew = 0.0f;

    for (int t = 0; t < T; t++) {
        if (wb < nb) {
            const int b = b0 + wb;
            const float* zsb = &sm.zs[wb][0][0];

            // ---- Stage 1: messages (mean) + projection (add) -> inc ----
            float incv = 0.0f;
            float* msbase = ms + ((size_t)b*T + t)*(EB*MB);
            for (int ep = 0; ep < 11; ep += 2) {
                const int sub = lane >> 4;
                const int eslot = ep + sub;
                const int m = lane & 15;
                if (eslot < 11) {
                    const int s = sm.slist[eslot];
                    const float* w    = &sm.mwT[eslot*528];
                    const float* zrow = &zsb[s*LB];
                    float mv = sm.mb[eslot*16 + m];
                    #pragma unroll
                    for (int k = 0; k < 32; k++) mv = fmaf(zrow[k], w[k*16 + m], mv);
                    sm.meanS[wb][sub][m] = mv;
                    msbase[(size_t)sm.elist[eslot]*MB + m] = mv;
                }
                __syncwarp();
                const int n2 = (ep + 1 < 11) ? 2 : 1;
                for (int ss = 0; ss < n2; ss++) {
                    const float* aw   = &sm.awT[(ep + ss)*512];
                    const float* mrow = sm.meanS[wb][ss];
                    #pragma unroll
                    for (int mm = 0; mm < 16; mm++)
                        incv = fmaf(mrow[mm], aw[mm*32 + lane], incv);
                }
                __syncwarp();
            }
            sm.incS[wb][lane] = incv;
            __syncwarp();

            const float* zrow   = &zsb[r*LB];
            const float* incrow = sm.incS[wb];

            // ---- Stage 2: flow ----
            float gv = sm.gsb[lane];
            #pragma unroll
            for (int i = 0; i < 32; i++) {
                gv = fmaf(zrow[i],   sm.gswT[i*32 + lane], gv);
                gv = fmaf(incrow[i], sm.gcwT[i*32 + lane], gv);
            }
            const float gate = fsig(gv);

            float a0 = sm.lb[2*lane], a1 = sm.lb[2*lane + 1];
            #pragma unroll
            for (int i = 0; i < 64; i++) {
                const float act = (i < 32) ? zrow[i] : incrow[i - 32];
                const float2 w2 = *reinterpret_cast<const float2*>(&sm.lwT[i*64 + 2*lane]);
                a0 = fmaf(act, w2.x, a0);
                a1 = fmaf(act, w2.y, a1);
            }
            a0 = a0 * fsig(a0);
            a1 = a1 * fsig(a1);
            sm.hbuf[wb][2*lane]     = a0;
            sm.hbuf[wb][2*lane + 1] = a1;
            __syncwarp();

            float tv = sm.ob[lane];
            #pragma unroll
            for (int o = 0; o < 64; o++)
                tv = fmaf(sm.hbuf[wb][o], sm.owT[o*32 + lane], tv);
            const float target = tanhf(tv);
            const float zold = zrow[lane];
            const float znew = fmaf(0.1f * gate, target - zold, zold);

            // ---- Stage 3: GRU (x = inc) ----
            float gi0 = sm.bih[lane], gi1 = sm.bih[32 + lane], gi2 = sm.bih[64 + lane];
            #pragma unroll
            for (int i = 0; i < 32; i++) {
                const float a = incrow[i];
                gi0 = fmaf(a, sm.wihT[i*96 + lane],      gi0);
                gi1 = fmaf(a, sm.wihT[i*96 + 32 + lane], gi1);
                gi2 = fmaf(a, sm.wihT[i*96 + 64 + lane], gi2);
            }
            const float* hrow = sm.hg[wb];
            float gh0 = sm.bhh[lane], gh1 = sm.bhh[32 + lane], gh2 = sm.bhh[64 + lane];
            #pragma unroll
            for (int i = 0; i < 32; i++) {
                const float a = hrow[i];
                gh0 = fmaf(a, sm.whhT[i*96 + lane],      gh0);
                gh1 = fmaf(a, sm.whhT[i*96 + 32 + lane], gh1);
                gh2 = fmaf(a, sm.whhT[i*96 + 64 + lane], gh2);
            }
            const float reset = fsig(gi0 + gh0);
            const float upd   = fsig(gi1 + gh1);
            const float nn    = tanhf(fmaf(reset, gh2, gi2));
            const float hold  = hrow[lane];
            hnew = (1.0f - upd) * nn + upd * hold;

            // ---- write-back ----
            zt[(((size_t)b*T + t)*RB + r)*LB + lane] = znew;
            __syncwarp();
            sm.hg[wb][lane]     = hnew;
            sm.zs[wb][r][lane]  = znew;
        }
        __syncthreads();

        // ---- inter-block barrier (12 blocks of this group) ----
        if (tid == 0) {
            __threadfence();
            atomicAdd(&g_bar[g], 1u);
            const unsigned tgtc = (unsigned)(RB * (t + 1));
            while (*((volatile unsigned*)&g_bar[g]) < tgtc) { }
        }
        __syncthreads();

        // ---- reload peer regions' z for next step ----
        if (t + 1 < T && wb < nb) {
            const int b = b0 + wb;
            const float* zsrc = zt + ((size_t)b*T + t)*RB*LB;
            #pragma unroll
            for (int rr = 0; rr < RB; rr++) {
                if (rr != r)
                    sm.zs[wb][rr][lane] = __ldcg(&zsrc[rr*LB + lane]);
            }
        }
        __syncwarp();
    }

    if (wb < nb) {
        const int b = b0 + wb;
        hf[((size_t)b*RB + r)*HHB + lane] = hnew;
    }
}

extern "C" void kernel_launch(void* const* d_in, const int* in_sizes, int n_in,
                              void* d_out, int out_size) {
    const float* z0     = (const float*)d_in[0];
    const float* h0     = (const float*)d_in[1];
    const float* mean_w = (const float*)d_in[2];
    const float* mean_b = (const float*)d_in[3];
    const float* add_w  = (const float*)d_in[4];
    const float* gsw    = (const float*)d_in[5];
    const float* gsb    = (const float*)d_in[6];
    const float* gcw    = (const float*)d_in[7];
    const float* lw     = (const float*)d_in[8];
    const float* lb     = (const float*)d_in[9];
    const float* ow     = (const float*)d_in[10];
    const float* ob     = (const float*)d_in[11];
    const float* wih    = (const float*)d_in[12];
    const float* whh    = (const float*)d_in[13];
    const float* bih    = (const float*)d_in[14];
    const float* bhh    = (const float*)d_in[15];
    const int* src_idx  = (const int*)d_in[16];
    const int* tgt_idx  = (const int*)d_in[17];
    // d_in[18] = n_steps (device scalar); derive T on host from out_size:
    // out_size = B*T*R*L + B*R*Hh + B*T*E*M = T*(24576+135168) + 24576
    const int per_t = BTOT*RB*LB + BTOT*EB*MB;       // 159744
    const int T = (out_size - BTOT*RB*HHB) / per_t;

    float* out = (float*)d_out;
    float* zt = out;                                  // (B,T,R,L)
    float* hf = zt + (size_t)BTOT * T * RB * LB;      // (B,R,Hh)
    float* ms = hf + (size_t)BTOT * RB * HHB;         // (B,T,E,M)

    cudaFuncSetAttribute(nv_main_kernel,
                         cudaFuncAttributeMaxDynamicSharedMemorySize,
                         (int)sizeof(SmemLayout));

    nv_init_kernel<<<1, 32>>>();
    nv_main_kernel<<<NBLOCKS, NTHREADS, sizeof(SmemLayout)>>>(
        z0, h0, mean_w, mean_b, add_w, gsw, gsb, gcw, lw, lb, ow, ob,
        wih, whh, bih, bhh, src_idx, tgt_idx, T, zt, hf, ms);
}

// round 2
// speedup vs baseline: 1.0689x; 1.0689x over previous
#include <cuda_runtime.h>
#include <cstddef>

// Problem constants (fixed by setup_inputs)
#define RB   12      // regions
#define LB   32      // latent
#define MB   16      // message dim
#define HHB  32      // GRU hidden
#define HFB  64      // flow hidden
#define EB   132     // edges = R*(R-1)
#define BTOT 64      // batch
#define NGROUP 12    // batch groups -> 144 blocks
#define NBLOCKS (NGROUP*RB)
#define NTHREADS 192 // 6 warps (max batches per group)
#define MAXWB 6

// per-(group, batch-warp, region) publication epoch
__device__ unsigned g_flag[NGROUP][MAXWB][RB];

struct __align__(16) SmemLayout {
    // weights, row-per-output, padded strides for conflict-free LDS.128
    float mw2[11*16*36];   // [slot][m][k], stride 36
    float aw2[11*32*20];   // [slot][l][m], stride 20
    float mb [11*16];
    float gsw2[32*36];     // [o][i]
    float gcw2[32*36];
    float gsb[32];
    float lw2[64*68];      // [o][i], i in 0..63
    float lbS[64];
    float ow2[32*68];      // [l][hf]
    float obS[32];
    float wih2[96*36];     // [j][i]
    float whh2[96*36];
    float bihS[96];
    float bhhS[96];
    // per-batch activations
    float zs  [MAXWB][RB][LB];
    float incS[MAXWB][LB];
    float hg  [MAXWB][HHB];
    float hbuf[MAXWB][HFB];
    float meanS[MAXWB][2][MB];
    int   elist[12];
    int   slist[12];
};

__device__ __forceinline__ float fsig(float x) { return 1.0f / (1.0f + __expf(-x)); }

__device__ __forceinline__ void st_release(unsigned* p, unsigned v) {
    asm volatile("st.release.gpu.u32 [%0], %1;" :: "l"(p), "r"(v) : "memory");
}
__device__ __forceinline__ unsigned ld_acquire(unsigned* p) {
    unsigned v;
    asm volatile("ld.acquire.gpu.u32 %0, [%1];" : "=r"(v) : "l"(p) : "memory");
    return v;
}

__global__ void nv_init_kernel() {
    unsigned* p = &g_flag[0][0][0];
    const int n = NGROUP*MAXWB*RB;
    for (int i = threadIdx.x; i < n; i += blockDim.x) p[i] = 0u;
}

__global__ void __launch_bounds__(NTHREADS, 1) nv_main_kernel(
    const float* __restrict__ z0,  const float* __restrict__ h0,
    const float* __restrict__ mean_w, const float* __restrict__ mean_b,
    const float* __restrict__ add_w,
    const float* __restrict__ gsw, const float* __restrict__ gsb_g,
    const float* __restrict__ gcw,
    const float* __restrict__ lw,  const float* __restrict__ lb_g,
    const float* __restrict__ ow,  const float* __restrict__ ob_g,
    const float* __restrict__ wih, const float* __restrict__ whh,
    const float* __restrict__ bih_g, const float* __restrict__ bhh_g,
    const int* __restrict__ src_idx, const int* __restrict__ tgt_idx,
    int T,
    float* __restrict__ zt, float* __restrict__ hf, float* __restrict__ ms)
{
    extern __shared__ char smraw[];
    SmemLayout& sm = *reinterpret_cast<SmemLayout*>(smraw);
    const int tid = threadIdx.x;
    const int g = blockIdx.x / RB;
    const int r = blockIdx.x % RB;

    const int nb = (g < 4) ? 6 : 5;                 // batches in this group
    const int b0 = g * 5 + (g < 4 ? g : 4);         // first batch index

    // ---- build incoming-edge list for region r ----
    for (int e = tid; e < EB; e += NTHREADS) {
        if (tgt_idx[e] == r) {
            int s = src_idx[e];
            int slot = (s < r) ? s : s - 1;
            sm.elist[slot] = e;
            sm.slist[slot] = s;
        }
    }
    __syncthreads();

    // ---- cache weights to smem (row-per-output, padded) ----
    for (int idx = tid; idx < 11*MB*LB; idx += NTHREADS) {
        int slot = idx / (MB*LB); int rem = idx % (MB*LB);
        int m = rem / LB, k = rem % LB;
        int e = sm.elist[slot];
        sm.mw2[(slot*16 + m)*36 + k] = mean_w[((size_t)e*MB + m)*LB + k];
    }
    for (int idx = tid; idx < 11*LB*MB; idx += NTHREADS) {
        int slot = idx / (LB*MB); int rem = idx % (LB*MB);
        int l = rem / MB, m = rem % MB;
        int e = sm.elist[slot];
        sm.aw2[(slot*32 + l)*20 + m] = add_w[((size_t)e*LB + l)*MB + m];
    }
    for (int idx = tid; idx < 11*MB; idx += NTHREADS) {
        int slot = idx / MB, m = idx % MB;
        sm.mb[idx] = mean_b[sm.elist[slot]*MB + m];
    }
    for (int idx = tid; idx < LB*LB; idx += NTHREADS) {
        int o = idx / LB, i = idx % LB;
        sm.gsw2[o*36 + i] = gsw[((size_t)r*LB + o)*LB + i];
        sm.gcw2[o*36 + i] = gcw[((size_t)r*LB + o)*LB + i];
    }
    if (tid < LB) sm.gsb[tid] = gsb_g[r*LB + tid];
    for (int idx = tid; idx < HFB*2*LB; idx += NTHREADS) {
        int o = idx / (2*LB), i = idx % (2*LB);
        sm.lw2[o*68 + i] = lw[((size_t)r*HFB + o)*(2*LB) + i];
    }
    if (tid < HFB) sm.lbS[tid] = lb_g[r*HFB + tid];
    for (int idx = tid; idx < LB*HFB; idx += NTHREADS) {
        int l = idx / HFB, i = idx % HFB;
        sm.ow2[l*68 + i] = ow[((size_t)r*LB + l)*HFB + i];
    }
    if (tid < LB) sm.obS[tid] = ob_g[r*LB + tid];
    for (int idx = tid; idx < 3*HHB*LB; idx += NTHREADS) {
        int j = idx / LB, i = idx % LB;
        sm.wih2[j*36 + i] = wih[((size_t)r*3*HHB + j)*LB + i];
        sm.whh2[j*36 + i] = whh[((size_t)r*3*HHB + j)*HHB + i];
    }
    if (tid < 96) { sm.bihS[tid] = bih_g[r*96 + tid]; sm.bhhS[tid] = bhh_g[r*96 + tid]; }

    // ---- init per-batch state ----
    const int wb   = tid >> 5;
    const int lane = tid & 31;
    if (wb < nb) {
        int b = b0 + wb;
        #pragma unroll
        for (int rr = 0; rr < RB; rr++)
            sm.zs[wb][rr][lane] = z0[((size_t)b*RB + rr)*LB + lane];
        sm.hg[wb][lane] = h0[((size_t)b*RB + r)*HHB + lane];
    }
    __syncthreads();

    if (wb >= nb) return;   // idle warps exit; no block-wide syncs remain

    const int b = b0 + wb;
    const int sub = lane >> 4;
    const int m16 = lane & 15;
    unsigned* myflag = &g_flag[g][wb][r];
    unsigned* grpflags = &g_flag[g][wb][0];

    float hnew = 0.0f;

    for (int t = 0; t < T; t++) {
        const float4* z4o = reinterpret_cast<const float4*>(&sm.zs[wb][r][0]);
        const float4* h4  = reinterpret_cast<const float4*>(&sm.hg[wb][0]);

        // ================= A: precompute from OWN state (overlaps peer wait) ====
        // GRU gh gates (depend on h only)
        float gh0a = sm.bhhS[lane],      gh0b = 0.f;
        float gh1a = sm.bhhS[32 + lane], gh1b = 0.f;
        float gh2a = sm.bhhS[64 + lane], gh2b = 0.f;
        {
            const float4* w0 = reinterpret_cast<const float4*>(&sm.whh2[(lane     )*36]);
            const float4* w1 = reinterpret_cast<const float4*>(&sm.whh2[(lane + 32)*36]);
            const float4* w2 = reinterpret_cast<const float4*>(&sm.whh2[(lane + 64)*36]);
            #pragma unroll
            for (int q = 0; q < 8; q++) {
                float4 a = h4[q];
                float4 x0 = w0[q], x1 = w1[q], x2 = w2[q];
                gh0a = fmaf(x0.x, a.x, gh0a); gh0b = fmaf(x0.y, a.y, gh0b);
                gh0a = fmaf(x0.z, a.z, gh0a); gh0b = fmaf(x0.w, a.w, gh0b);
                gh1a = fmaf(x1.x, a.x, gh1a); gh1b = fmaf(x1.y, a.y, gh1b);
                gh1a = fmaf(x1.z, a.z, gh1a); gh1b = fmaf(x1.w, a.w, gh1b);
                gh2a = fmaf(x2.x, a.x, gh2a); gh2b = fmaf(x2.y, a.y, gh2b);
                gh2a = fmaf(x2.z, a.z, gh2a); gh2b = fmaf(x2.w, a.w, gh2b);
            }
        }
        const float gh_r = gh0a + gh0b, gh_z = gh1a + gh1b, gh_n = gh2a + gh2b;

        // gate state term (own z)
        float gvsa = sm.gsb[lane], gvsb = 0.f;
        {
            const float4* w = reinterpret_cast<const float4*>(&sm.gsw2[lane*36]);
            #pragma unroll
            for (int q = 0; q < 8; q++) {
                float4 a = z4o[q], x = w[q];
                gvsa = fmaf(x.x, a.x, gvsa); gvsb = fmaf(x.y, a.y, gvsb);
                gvsa = fmaf(x.z, a.z, gvsa); gvsb = fmaf(x.w, a.w, gvsb);
            }
        }

        // hidden layer z-half partials (outputs lane and lane+32)
        float p0a = sm.lbS[lane],      p0b = 0.f;
        float p1a = sm.lbS[lane + 32], p1b = 0.f;
        {
            const float4* w0 = reinterpret_cast<const float4*>(&sm.lw2[(lane     )*68]);
            const float4* w1 = reinterpret_cast<const float4*>(&sm.lw2[(lane + 32)*68]);
            #pragma unroll
            for (int q = 0; q < 8; q++) {
                float4 a = z4o[q];
                float4 x0 = w0[q], x1 = w1[q];
                p0a = fmaf(x0.x, a.x, p0a); p0b = fmaf(x0.y, a.y, p0b);
                p0a = fmaf(x0.z, a.z, p0a); p0b = fmaf(x0.w, a.w, p0b);
                p1a = fmaf(x1.x, a.x, p1a); p1b = fmaf(x1.y, a.y, p1b);
                p1a = fmaf(x1.z, a.z, p1a); p1b = fmaf(x1.w, a.w, p1b);
            }
        }

        // ================= B: wait for peers' z(t-1) and load them =============
        if (t > 0) {
            const unsigned need = (unsigned)t;
            for (;;) {
                unsigned v = need;
                if (lane < RB) v = ld_acquire(&grpflags[lane]);
                if (__all_sync(0xffffffffu, v >= need)) break;
            }
            const float* zsrc = zt + ((size_t)b*T + (t - 1))*RB*LB;
            #pragma unroll
            for (int rr = 0; rr < RB; rr++) {
                if (rr != r)
                    sm.zs[wb][rr][lane] = __ldcg(&zsrc[rr*LB + lane]);
            }
            __syncwarp();
        }

        // ================= C: stage 1 — messages + projection -> inc ==========
        float inc0 = 0.f, inc1 = 0.f, inc2 = 0.f, inc3 = 0.f;
        float* msbase = ms + ((size_t)b*T + t)*(EB*MB);
        for (int ep = 0; ep < 11; ep += 2) {
            const int eslot = ep + sub;
            if (eslot < 11) {
                const int s = sm.slist[eslot];
                const float4* w4 = reinterpret_cast<const float4*>(&sm.mw2[(eslot*16 + m16)*36]);
                const float4* a4 = reinterpret_cast<const float4*>(&sm.zs[wb][s][0]);
                float acc0 = sm.mb[eslot*16 + m16], acc1 = 0.f;
                #pragma unroll
                for (int q = 0; q < 8; q++) {
                    float4 w = w4[q], a = a4[q];
                    acc0 = fmaf(w.x, a.x, acc0); acc1 = fmaf(w.y, a.y, acc1);
                    acc0 = fmaf(w.z, a.z, acc0); acc1 = fmaf(w.w, a.w, acc1);
                }
                const float mv = acc0 + acc1;
                sm.meanS[wb][sub][m16] = mv;
                msbase[(size_t)sm.elist[eslot]*MB + m16] = mv;
            }
            __syncwarp();
            const int n2 = (ep + 1 < 11) ? 2 : 1;
            for (int ss = 0; ss < n2; ss++) {
                const float4* w4 = reinterpret_cast<const float4*>(&sm.aw2[((ep + ss)*32 + lane)*20]);
                const float4* a4 = reinterpret_cast<const float4*>(&sm.meanS[wb][ss][0]);
                #pragma unroll
                for (int q = 0; q < 4; q++) {
                    float4 w = w4[q], a = a4[q];
                    inc0 = fmaf(w.x, a.x, inc0); inc1 = fmaf(w.y, a.y, inc1);
                    inc2 = fmaf(w.z, a.z, inc2); inc3 = fmaf(w.w, a.w, inc3);
                }
            }
            __syncwarp();
        }
        const float incv = (inc0 + inc1) + (inc2 + inc3);
        sm.incS[wb][lane] = incv;
        __syncwarp();
        const float4* inc4 = reinterpret_cast<const float4*>(&sm.incS[wb][0]);

        // ================= D: gate cond term + gate ===========================
        {
            const float4* w = reinterpret_cast<const float4*>(&sm.gcw2[lane*36]);
            #pragma unroll
            for (int q = 0; q < 8; q++) {
                float4 a = inc4[q], x = w[q];
                gvsa = fmaf(x.x, a.x, gvsa); gvsb = fmaf(x.y, a.y, gvsb);
                gvsa = fmaf(x.z, a.z, gvsa); gvsb = fmaf(x.w, a.w, gvsb);
            }
        }
        const float gate = fsig(gvsa + gvsb);

        // ================= E: hidden inc-half, silu, out layer, z update ======
        {
            const float4* w0 = reinterpret_cast<const float4*>(&sm.lw2[(lane     )*68 + 32]);
            const float4* w1 = reinterpret_cast<const float4*>(&sm.lw2[(lane + 32)*68 + 32]);
            #pragma unroll
            for (int q = 0; q < 8; q++) {
                float4 a = inc4[q];
                float4 x0 = w0[q], x1 = w1[q];
                p0a = fmaf(x0.x, a.x, p0a); p0b = fmaf(x0.y, a.y, p0b);
                p0a = fmaf(x0.z, a.z, p0a); p0b = fmaf(x0.w, a.w, p0b);
                p1a = fmaf(x1.x, a.x, p1a); p1b = fmaf(x1.y, a.y, p1b);
                p1a = fmaf(x1.z, a.z, p1a); p1b = fmaf(x1.w, a.w, p1b);
            }
        }
        const float pv0 = p0a + p0b, pv1 = p1a + p1b;
        sm.hbuf[wb][lane]      = pv0 * fsig(pv0);
        sm.hbuf[wb][lane + 32] = pv1 * fsig(pv1);
        __syncwarp();

        float tva = sm.obS[lane], tvb = 0.f, tvc = 0.f, tvd = 0.f;
        {
            const float4* w = reinterpret_cast<const float4*>(&sm.ow2[lane*68]);
            const float4* a4 = reinterpret_cast<const float4*>(&sm.hbuf[wb][0]);
            #pragma unroll
            for (int q = 0; q < 16; q++) {
                float4 a = a4[q], x = w[q];
                tva = fmaf(x.x, a.x, tva); tvb = fmaf(x.y, a.y, tvb);
                tvc = fmaf(x.z, a.z, tvc); tvd = fmaf(x.w, a.w, tvd);
            }
        }
        const float target = tanhf((tva + tvb) + (tvc + tvd));
        const float zold = sm.zs[wb][r][lane];
        const float znew = fmaf(0.1f * gate, target - zold, zold);

        // publish z ASAP (peers only need z, not h)
        zt[(((size_t)b*T + t)*RB + r)*LB + lane] = znew;
        __syncwarp();
        if (lane == 0) st_release(myflag, (unsigned)(t + 1));

        // ================= F: GRU (off the inter-block critical path) =========
        sm.zs[wb][r][lane] = znew;
        float gi0a = sm.bihS[lane],      gi0b = 0.f;
        float gi1a = sm.bihS[32 + lane], gi1b = 0.f;
        float gi2a = sm.bihS[64 + lane], gi2b = 0.f;
        {
            const float4* w0 = reinterpret_cast<const float4*>(&sm.wih2[(lane     )*36]);
            const float4* w1 = reinterpret_cast<const float4*>(&sm.wih2[(lane + 32)*36]);
            const float4* w2 = reinterpret_cast<const float4*>(&sm.wih2[(lane + 64)*36]);
            #pragma unroll
            for (int q = 0; q < 8; q++) {
                float4 a = inc4[q];
                float4 x0 = w0[q], x1 = w1[q], x2 = w2[q];
                gi0a = fmaf(x0.x, a.x, gi0a); gi0b = fmaf(x0.y, a.y, gi0b);
                gi0a = fmaf(x0.z, a.z, gi0a); gi0b = fmaf(x0.w, a.w, gi0b);
                gi1a = fmaf(x1.x, a.x, gi1a); gi1b = fmaf(x1.y, a.y, gi1b);
                gi1a = fmaf(x1.z, a.z, gi1a); gi1b = fmaf(x1.w, a.w, gi1b);
                gi2a = fmaf(x2.x, a.x, gi2a); gi2b = fmaf(x2.y, a.y, gi2b);
                gi2a = fmaf(x2.z, a.z, gi2a); gi2b = fmaf(x2.w, a.w, gi2b);
            }
        }
        const float reset = fsig((gi0a + gi0b) + gh_r);
        const float upd   = fsig((gi1a + gi1b) + gh_z);
        const float nn    = tanhf(fmaf(reset, gh_n, gi2a + gi2b));
        const float hold  = sm.hg[wb][lane];
        hnew = (1.0f - upd) * nn + upd * hold;
        sm.hg[wb][lane] = hnew;
        __syncwarp();
    }

    hf[((size_t)b*RB + r)*HHB + lane] = hnew;
}

extern "C" void kernel_launch(void* const* d_in, const int* in_sizes, int n_in,
                              void* d_out, int out_size) {
    const float* z0     = (const float*)d_in[0];
    const float* h0     = (const float*)d_in[1];
    const float* mean_w = (const float*)d_in[2];
    const float* mean_b = (const float*)d_in[3];
    const float* add_w  = (const float*)d_in[4];
    const float* gsw    = (const float*)d_in[5];
    const float* gsb    = (const float*)d_in[6];
    const float* gcw    = (const float*)d_in[7];
    const float* lw     = (const float*)d_in[8];
    const float* lb     = (const float*)d_in[9];
    const float* ow     = (const float*)d_in[10];
    const float* ob     = (const float*)d_in[11];
    const float* wih    = (const float*)d_in[12];
    const float* whh    = (const float*)d_in[13];
    const float* bih    = (const float*)d_in[14];
    const float* bhh    = (const float*)d_in[15];
    const int* src_idx  = (const int*)d_in[16];
    const int* tgt_idx  = (const int*)d_in[17];
    // derive T on host from out_size:
    // out_size = B*T*R*L + B*R*Hh + B*T*E*M
    const int per_t = BTOT*RB*LB + BTOT*EB*MB;       // 159744
    const int T = (out_size - BTOT*RB*HHB) / per_t;

    float* out = (float*)d_out;
    float* zt = out;                                  // (B,T,R,L)
    float* hf = zt + (size_t)BTOT * T * RB * LB;      // (B,R,Hh)
    float* ms = hf + (size_t)BTOT * RB * HHB;         // (B,T,E,M)

    cudaFuncSetAttribute(nv_main_kernel,
                         cudaFuncAttributeMaxDynamicSharedMemorySize,
                         (int)sizeof(SmemLayout));

    nv_init_kernel<<<1, 256>>>();
    nv_main_kernel<<<NBLOCKS, NTHREADS, sizeof(SmemLayout)>>>(
        z0, h0, mean_w, mean_b, add_w, gsw, gsb, gcw, lw, lb, ow, ob,
        wih, whh, bih, bhh, src_idx, tgt_idx, T, zt, hf, ms);
}